// round 6
// baseline (speedup 1.0000x reference)
#include <cuda_runtime.h>

// axon_layer: dual-exponential PSP scan.
//   m_t = m_{t-1}*dm + x_t ; s_t = s_{t-1}*ds + x_t ; psp_t = (m_t - s_t)*v0
//
// Warp-private full-row pipeline: each warp owns 16 tiles of 32 consecutive
// FULL rows (T=400). A tile is a contiguous 51.2 KB gmem slab on both the
// load and store side (rows are contiguous in [B,F,T]) -> long DRAM bursts.
// Per-warp double-buffered cp.async pipeline, no __syncthreads anywhere.
//
// Inputs: [0] input_spikes f32 [B,F,T]  [1] decay_m f32 [F]
//         [2] decay_s f32 [F]           [3] v_0 f32 scalar
// Output: psps [B,F,T] then m_T [B,F] then s_T [B,F].

#define AXT     400
#define AXRQ    100                    // float4 per row
#define AXROWS  32                     // rows per warp-tile
#define AXSTR   101                    // padded smem row stride in float4
#define AXTILEQ (AXROWS * AXRQ)        // 3200 quads = 51.2 KB per tile
#define AXBUFQ  (AXROWS * AXSTR)       // 3232 quads padded
#define AXBLK   64                     // 2 warps per block
#define AXGRID  128                    // 256 warps total

__device__ __forceinline__ void ax_cp_async16(void* smem_dst, const void* gmem_src) {
    unsigned saddr = (unsigned)__cvta_generic_to_shared(smem_dst);
    asm volatile("cp.async.cg.shared.global [%0], [%1], 16;\n"
                 :: "r"(saddr), "l"(gmem_src));
}
__device__ __forceinline__ void ax_cp_commit() {
    asm volatile("cp.async.commit_group;\n");
}
template <int N>
__device__ __forceinline__ void ax_cp_wait() {
    asm volatile("cp.async.wait_group %0;\n" :: "n"(N));
}

extern __shared__ float4 ax_smem[];    // [2 warps][2 bufs][AXBUFQ] = 206848 B

// Load one full tile (contiguous 51.2 KB slab) into padded smem buffer.
__device__ __forceinline__ void ax_issue_tile(float4* __restrict__ buf,
                                              const float4* __restrict__ g,
                                              int lane)
{
#pragma unroll
    for (int i = 0; i < AXRQ; ++i) {
        int q = i * 32 + lane;             // linear quad in tile [0, 3200)
        int pad = q + q / AXRQ;            // padded index = q + row
        ax_cp_async16(&buf[pad], &g[q]);
    }
    ax_cp_commit();
}

__global__ void __launch_bounds__(AXBLK)
axon_warp_kernel(const float* __restrict__ x,
                 const float* __restrict__ decay_m,
                 const float* __restrict__ decay_s,
                 const float* __restrict__ v0p,
                 float* __restrict__ out,
                 int F, long long n_rows, int tiles_per_warp)
{
    const int lane = threadIdx.x & 31;
    const int wid  = threadIdx.x >> 5;
    const float v0 = __ldg(v0p);

    float4* buf0 = ax_smem + (wid * 2    ) * AXBUFQ;
    float4* buf1 = ax_smem + (wid * 2 + 1) * AXBUFQ;

    const long long wg    = (long long)blockIdx.x * 2 + wid;
    const long long tile0 = wg * tiles_per_warp;          // blocked assignment

    const float4* __restrict__ gin4  = (const float4*)x;
    float4* __restrict__       gout4 = (float4*)out;
    const long long psps = n_rows * AXT;

    // ---- prologue: tiles 0 and 1 in flight (warp-private groups) ----
    ax_issue_tile(buf0, gin4 + tile0 * AXTILEQ, lane);
    if (tiles_per_warp >= 2)
        ax_issue_tile(buf1, gin4 + (tile0 + 1) * AXTILEQ, lane);

    const int rbase = lane * AXSTR;

    for (int k = 0; k < tiles_per_warp; ++k) {
        float4* buf = (k & 1) ? buf1 : buf0;
        const long long tile = tile0 + k;

        if (k == tiles_per_warp - 1) ax_cp_wait<0>();   // last: drain fully
        else                         ax_cp_wait<1>();   // tile k resident
        __syncwarp();

        // ---- per-lane sequential scan of one full row (bit-exact) ----
        const long long row = tile * AXROWS + lane;
        const float dm = __ldg(&decay_m[(int)(row % F)]);
        const float ds = __ldg(&decay_s[(int)(row % F)]);
        float m = 0.0f, s = 0.0f;

#pragma unroll 4
        for (int t4 = 0; t4 < AXRQ; ++t4) {
            float4 q = buf[rbase + t4];
            float4 o;
            m = fmaf(m, dm, q.x); s = fmaf(s, ds, q.x); o.x = (m - s) * v0;
            m = fmaf(m, dm, q.y); s = fmaf(s, ds, q.y); o.y = (m - s) * v0;
            m = fmaf(m, dm, q.z); s = fmaf(s, ds, q.z); o.z = (m - s) * v0;
            m = fmaf(m, dm, q.w); s = fmaf(s, ds, q.w); o.w = (m - s) * v0;
            buf[rbase + t4] = o;
        }
        __syncwarp();

        // ---- store: contiguous 51.2 KB slab, coalesced ----
        float4* __restrict__ gt = gout4 + tile * AXTILEQ;
#pragma unroll
        for (int i = 0; i < AXRQ; ++i) {
            int q = i * 32 + lane;
            gt[q] = buf[q + q / AXRQ];
        }

        // final states for this lane's row
        out[psps + row]          = m;
        out[psps + n_rows + row] = s;

        __syncwarp();                       // buffer fully read -> reusable

        if (k + 2 < tiles_per_warp)
            ax_issue_tile(buf, gin4 + (tile + 2) * AXTILEQ, lane);
    }
}

extern "C" void kernel_launch(void* const* d_in, const int* in_sizes, int n_in,
                              void* d_out, int out_size)
{
    const float* x   = (const float*)d_in[0];
    const float* dmv = (const float*)d_in[1];
    const float* dsv = (const float*)d_in[2];
    const float* v0p = (const float*)d_in[3];
    float* out = (float*)d_out;

    const int F = in_sizes[1];                       // 4096
    const long long total = (long long)in_sizes[0];  // B*F*T
    const long long n_rows = total / AXT;            // 131072
    const long long ntiles = n_rows / AXROWS;        // 4096

    int grid = AXGRID;                               // 256 warps
    long long total_warps = (long long)grid * 2;
    int tpw;
    if (ntiles % total_warps == 0) {
        tpw = (int)(ntiles / total_warps);           // 16
    } else {                                         // generic fallback
        grid = (int)((ntiles + 1) / 2);
        tpw = 1;
    }

    const int smem_bytes = 4 * AXBUFQ * (int)sizeof(float4);  // 206848

    static bool attr_set = false;
    if (!attr_set) {
        cudaFuncSetAttribute(axon_warp_kernel,
                             cudaFuncAttributeMaxDynamicSharedMemorySize,
                             smem_bytes);
        attr_set = true;
    }

    axon_warp_kernel<<<grid, AXBLK, smem_bytes>>>(
        x, dmv, dsv, v0p, out, F, n_rows, tpw);
}